// round 8
// baseline (speedup 1.0000x reference)
#include <cuda_runtime.h>
#include <cstdint>

// Problem constants
#define N_ 2
#define C_ 64
#define M_ 4800
#define K_ 64
#define EPS_ 1e-5f

typedef unsigned long long ull;

// ---------------- device scratch (no allocation allowed) ----------------
__device__ __align__(16) float g_B0t[N_ * M_ * C_];  // s0[c]*(W0q@query), [n][m][c]
__device__ __align__(16) float g_A0p[N_ * C_ * K_];  // s0*(W0s@scene)+t0  [n][c][k]
__device__ __align__(16) float g_Ts [N_ * C_ * K_];  // Wskip_xyz @ sx     [n][c][k]
__device__ __align__(16) float g_T1a[N_ * C_ * K_];  // s1a*(W1a_xyz@sx)+t1a [n][c][k]
// duplicated-weight images: ull = (w, w) packed, layout [j][c]
__device__ __align__(16) ull g_WsD[C_ * C_];
__device__ __align__(16) ull g_WaD[C_ * C_];         // s1a-folded
__device__ __align__(16) ull g_WbD[C_ * C_];         // s1b-folded
__device__ __align__(16) ull g_t1bD[C_];
__device__ float g_s0[C_], g_t0[C_], g_s1a[C_], g_t1a[C_];

// ---------------- f32x2 helpers ----------------
__device__ __forceinline__ void ffma2(ull& d, ull a, ull b) {
    asm("fma.rn.f32x2 %0, %1, %2, %0;" : "+l"(d) : "l"(a), "l"(b));
}
__device__ __forceinline__ ull dup2(float w) {
    ull r;
    asm("mov.b64 %0, {%1, %1};" : "=l"(r) : "f"(w));
    return r;
}
__device__ __forceinline__ float2 unpack2(ull v) {
    float2 r;
    asm("mov.b64 {%0, %1}, %2;" : "=f"(r.x), "=f"(r.y) : "l"(v));
    return r;
}

// ---------------- prep 1: BN folds + duplicated/scaled weights ----------------
__global__ void prep_weights(
    const float* __restrict__ W1a, const float* __restrict__ W1b,
    const float* __restrict__ Wskip,
    const float* __restrict__ g0, const float* __restrict__ b0,
    const float* __restrict__ m0, const float* __restrict__ v0,
    const float* __restrict__ g1a, const float* __restrict__ b1a,
    const float* __restrict__ m1a, const float* __restrict__ v1a,
    const float* __restrict__ g1b, const float* __restrict__ b1b,
    const float* __restrict__ m1b, const float* __restrict__ v1b)
{
    __shared__ float s1a_s[C_], s1b_s[C_];
    int t = threadIdx.x;
    if (t < C_) {
        float s = g0[t] * rsqrtf(v0[t] + EPS_);
        g_s0[t] = s; g_t0[t] = b0[t] - m0[t] * s;
        float sa = g1a[t] * rsqrtf(v1a[t] + EPS_);
        s1a_s[t] = sa; g_s1a[t] = sa; g_t1a[t] = b1a[t] - m1a[t] * sa;
        float sb = g1b[t] * rsqrtf(v1b[t] + EPS_);
        s1b_s[t] = sb;
        g_t1bD[t] = dup2(b1b[t] - m1b[t] * sb);
    }
    __syncthreads();
    for (int i = t; i < C_ * C_; i += blockDim.x) {
        int j = i >> 6, c = i & 63;          // [j][c]
        g_WsD[i] = dup2(Wskip[c * 67 + j]);
        g_WaD[i] = dup2(s1a_s[c] * W1a[c * 67 + j]);
        g_WbD[i] = dup2(s1b_s[c] * W1b[c * 64 + j]);
    }
}

// ---------------- prep 2: per-(n,k) tensors (A0', Ts, T1a') ----------------
__global__ void prep_nk(
    const float* __restrict__ scene_rgb,   // (N,C,1,K)
    const float* __restrict__ scene_xyz,   // (N,3,1,K)
    const float* __restrict__ mask,        // (N,1,1,K)
    const float* __restrict__ W0,          // (C,2C)
    const float* __restrict__ W1a,         // (C,C+3)
    const float* __restrict__ Wskip)       // (C,C+3)
{
    int gid = blockIdx.x * blockDim.x + threadIdx.x;   // 0 .. N*C*K-1 = 8191
    int n = gid >> 12;
    int r = gid & 4095;
    int c = r >> 6;
    int k = r & 63;
    const float* sc = scene_rgb + n * C_ * K_;
    float acc = 0.f;
#pragma unroll 8
    for (int j = 0; j < C_; ++j)
        acc = fmaf(W0[c * 2 * C_ + j], sc[j * K_ + k], acc);
    g_A0p[gid] = g_s0[c] * acc + g_t0[c];

    float mk = mask[n * K_ + k];
    float x0 = scene_xyz[n * 3 * K_ + 0 * K_ + k] * mk;
    float x1 = scene_xyz[n * 3 * K_ + 1 * K_ + k] * mk;
    float x2 = scene_xyz[n * 3 * K_ + 2 * K_ + k] * mk;
    g_Ts[gid]  = Wskip[c * 67 + 64] * x0 + Wskip[c * 67 + 65] * x1 +
                 Wskip[c * 67 + 66] * x2;
    g_T1a[gid] = g_s1a[c] * (W1a[c * 67 + 64] * x0 + W1a[c * 67 + 65] * x1 +
                             W1a[c * 67 + 66] * x2) + g_t1a[c];
}

// ---------------- prep 3: B0t[n][m][c] (transposed, smem-tiled) ----------------
__global__ void __launch_bounds__(128) prep_B0t(
    const float* __restrict__ query,   // (N,C,M,1)
    const float* __restrict__ W0)      // (C,2C)
{
    __shared__ float sq[64 * 32];
    __shared__ float sw[64 * 64];
    const int tid = threadIdx.x;
    const int bid = blockIdx.x;
    const int n = bid / 150;
    const int m0 = (bid % 150) * 32;

    for (int i = tid; i < 4096; i += 128) {
        int c = i >> 6, j = i & 63;
        sw[j * 64 + c] = W0[c * 2 * C_ + C_ + j];
    }
    const float* qn = query + n * C_ * M_;
    for (int i = tid; i < 2048; i += 128) {
        int j = i >> 5, ml = i & 31;
        sq[i] = qn[j * M_ + m0 + ml];
    }
    __syncthreads();

    const int ml = tid & 31;
    const int cg = tid >> 5;
    float acc[16];
#pragma unroll
    for (int i = 0; i < 16; ++i) acc[i] = 0.f;
#pragma unroll 4
    for (int j = 0; j < 64; ++j) {
        float qv = sq[j * 32 + ml];
        const float4* wr = reinterpret_cast<const float4*>(sw + j * 64 + cg * 16);
        float4 w0 = wr[0], w1 = wr[1], w2 = wr[2], w3 = wr[3];
        float wv[16] = {w0.x, w0.y, w0.z, w0.w, w1.x, w1.y, w1.z, w1.w,
                        w2.x, w2.y, w2.z, w2.w, w3.x, w3.y, w3.z, w3.w};
#pragma unroll
        for (int ci = 0; ci < 16; ++ci)
            acc[ci] = fmaf(wv[ci], qv, acc[ci]);
    }
    float* outp = g_B0t + n * M_ * C_ + (m0 + ml) * C_ + cg * 16;
#pragma unroll
    for (int ci = 0; ci < 16; ++ci)
        outp[ci] = acc[ci] * g_s0[cg * 16 + ci];
}

// ---------------- fused main kernel ----------------
// 512 threads, 1 CTA/SM, Tm=4 m's per tile, 2 tiles per CTA (grid 1200).
// Warp w: c-block cb=(w&7)*8; mi = (w>>3)*2 + (lane>>4); lane tk=lane&15
// owns k = tk*4..+3 (two natural f32x2 pairs).
// All FFMA2 operands come directly from 128-bit smem loads:
//   H: ulonglong2 (natural k-pairs), W: ulonglong2 of (w,w)-duplicated pairs
//   (broadcast). No dup movs in the GEMM loops.
// smem (floats): sWsD[4096 ull]@0, sWaD@8192, sWbD@16384 (as float idx),
//                sH[4*64*64]@24576, sF[4*64]@40960
#define SMEM_FLOATS (24576 + 16384 + 256)

extern "C" __global__ void __launch_bounds__(512, 1) fused_main(
    const float* __restrict__ pre_xyz,   // (N,3,M)
    const float* __restrict__ Wout,      // (3,C+3)
    float* __restrict__ out)             // (N,3,M)
{
    extern __shared__ float smem[];
    ull*   sWsD = reinterpret_cast<ull*>(smem);           // [j*64 + c]
    ull*   sWaD = reinterpret_cast<ull*>(smem + 8192);
    ull*   sWbD = reinterpret_cast<ull*>(smem + 16384);
    float* sH   = smem + 24576;                            // [mi*4096 + j*64 + k]
    float* sF   = smem + 40960;                            // [mi*64 + c]

    const int tid  = threadIdx.x;
    const int lane = tid & 31;
    const int w    = tid >> 5;              // 0..15
    const int cb   = (w & 7) * 8;           // 8 c's per warp
    const int miA  = ((w >> 3) << 1) + (lane >> 4);   // absolute mi 0..3
    const int tk   = lane & 15;
    const int kb   = tk * 4;

    // ---- one-time: stage duplicated weights (96KB) ----
    {
        const ulonglong2* s1 = (const ulonglong2*)g_WsD;
        const ulonglong2* s2 = (const ulonglong2*)g_WaD;
        const ulonglong2* s3 = (const ulonglong2*)g_WbD;
        ulonglong2* d1 = (ulonglong2*)sWsD;
        ulonglong2* d2 = (ulonglong2*)sWaD;
        ulonglong2* d3 = (ulonglong2*)sWbD;
        for (int i = tid; i < 2048; i += 512) {
            d1[i] = s1[i]; d2[i] = s2[i]; d3[i] = s3[i];
        }
    }

    // t1b dup'd bias for this warp's c-block (8 ULLs, L2/L1 broadcast)
    ull tbD[8];
#pragma unroll
    for (int ci = 0; ci < 8; ++ci) tbD[ci] = g_t1bD[cb + ci];

    // hoisted output weights: warp w<12 handles (mi=w/3, o=w%3)
    float wo0 = 0.f, wo1 = 0.f, wx = 0.f, wy = 0.f, wz = 0.f;
    const int fo_mi = w / 3, fo_o = w - fo_mi * 3;
    if (w < 12) {
        wo0 = Wout[fo_o * 67 + lane];
        wo1 = Wout[fo_o * 67 + 32 + lane];
        wx  = Wout[fo_o * 67 + 64];
        wy  = Wout[fo_o * 67 + 65];
        wz  = Wout[fo_o * 67 + 66];
    }

    for (int it = 0; it < 2; ++it) {
        const int t  = blockIdx.x + it * 1200;      // 0..2399
        const int n  = t / 600;                     // 600 tiles (of 4 m) per n... 
        // careful: tiles per n = 4800/4 = 1200; total 2400; n = t/1200
        const int n_ = t / 1200;
        const int m0 = (t - n_ * 1200) * 4;
        (void)n;

        const float* A0n = g_A0p + n_ * 4096;
        const float* B0n = g_B0t + n_ * M_ * C_;
        const float* TsN  = g_Ts  + n_ * 4096;
        const float* T1aN = g_T1a + n_ * 4096;

        __syncthreads();   // prior-tile consumers of sH/sF done

        // ---- Phase A: H[mi][j][k] = relu(A0p[j][k] + B0t[m0+mi][j]) ----
#pragma unroll
        for (int g = 0; g < 8; ++g) {
            int idx = tid + g * 512;        // 0..4095
            int mi = idx >> 10;
            int r  = idx & 1023;
            int j  = r >> 4;
            int kq = r & 15;
            float4 a = *(const float4*)(A0n + j * 64 + kq * 4);
            float  b = B0n[(m0 + mi) * C_ + j];
            float4 h;
            h.x = fmaxf(a.x + b, 0.f);
            h.y = fmaxf(a.y + b, 0.f);
            h.z = fmaxf(a.z + b, 0.f);
            h.w = fmaxf(a.w + b, 0.f);
            *(float4*)(sH + mi * 4096 + j * 64 + kq * 4) = h;
        }

        // ---- bias init: natural k-pairs from global (L1/L2 resident) ----
        ull accS[16], accA[16];   // [ci*2 + kp]
#pragma unroll
        for (int ci = 0; ci < 8; ++ci) {
            ulonglong2 ts = *(const ulonglong2*)(TsN  + (cb + ci) * 64 + kb);
            ulonglong2 ta = *(const ulonglong2*)(T1aN + (cb + ci) * 64 + kb);
            accS[ci * 2 + 0] = ts.x; accS[ci * 2 + 1] = ts.y;
            accA[ci * 2 + 0] = ta.x; accA[ci * 2 + 1] = ta.y;
        }
        __syncthreads();

        // ---- Phase B: skip + fcn1a GEMMs (pure LDS.128 + FFMA2) ----
        const float* hbase = sH + miA * 4096 + kb;
#pragma unroll 2
        for (int j = 0; j < 64; ++j) {
            ulonglong2 h = *(const ulonglong2*)(hbase + j * 64);
            const ulonglong2* wsr = (const ulonglong2*)(sWsD + j * 64 + cb);
            const ulonglong2* war = (const ulonglong2*)(sWaD + j * 64 + cb);
            ulonglong2 ws01 = wsr[0], ws23 = wsr[1], ws45 = wsr[2], ws67 = wsr[3];
            ulonglong2 wa01 = war[0], wa23 = war[1], wa45 = war[2], wa67 = war[3];
            ull wsv[8] = {ws01.x, ws01.y, ws23.x, ws23.y,
                          ws45.x, ws45.y, ws67.x, ws67.y};
            ull wav[8] = {wa01.x, wa01.y, wa23.x, wa23.y,
                          wa45.x, wa45.y, wa67.x, wa67.y};
#pragma unroll
            for (int ci = 0; ci < 8; ++ci) {
                ffma2(accS[ci * 2 + 0], wsv[ci], h.x);
                ffma2(accS[ci * 2 + 1], wsv[ci], h.y);
                ffma2(accA[ci * 2 + 0], wav[ci], h.x);
                ffma2(accA[ci * 2 + 1], wav[ci], h.y);
            }
        }
        __syncthreads();   // all reads of H done before overwrite

        // ---- Phase C: H1 = relu(accA) -> sH (natural layout) ----
#pragma unroll
        for (int ci = 0; ci < 8; ++ci) {
            float2 f0 = unpack2(accA[ci * 2 + 0]);
            float2 f1 = unpack2(accA[ci * 2 + 1]);
            float4 h1v;
            h1v.x = fmaxf(f0.x, 0.f);
            h1v.y = fmaxf(f0.y, 0.f);
            h1v.z = fmaxf(f1.x, 0.f);
            h1v.w = fmaxf(f1.y, 0.f);
            *(float4*)(sH + miA * 4096 + (cb + ci) * 64 + kb) = h1v;
        }
        __syncthreads();

        // ---- Phase D: fcn1b GEMM ----
        ull accB[16];
#pragma unroll
        for (int ci = 0; ci < 8; ++ci) {
            accB[ci * 2 + 0] = tbD[ci];
            accB[ci * 2 + 1] = tbD[ci];
        }
#pragma unroll 2
        for (int j = 0; j < 64; ++j) {
            ulonglong2 h = *(const ulonglong2*)(hbase + j * 64);
            const ulonglong2* wbr = (const ulonglong2*)(sWbD + j * 64 + cb);
            ulonglong2 wb01 = wbr[0], wb23 = wbr[1], wb45 = wbr[2], wb67 = wbr[3];
            ull wbv[8] = {wb01.x, wb01.y, wb23.x, wb23.y,
                          wb45.x, wb45.y, wb67.x, wb67.y};
#pragma unroll
            for (int ci = 0; ci < 8; ++ci) {
                ffma2(accB[ci * 2 + 0], wbv[ci], h.x);
                ffma2(accB[ci * 2 + 1], wbv[ci], h.y);
            }
        }

        // ---- Phase E: F = relu(accB) + accS; max over 4 k; shfl over 16 ----
        float mx[8];
#pragma unroll
        for (int ci = 0; ci < 8; ++ci) {
            float2 b0 = unpack2(accB[ci * 2 + 0]);
            float2 b1 = unpack2(accB[ci * 2 + 1]);
            float2 s0 = unpack2(accS[ci * 2 + 0]);
            float2 s1 = unpack2(accS[ci * 2 + 1]);
            float v0 = fmaxf(b0.x, 0.f) + s0.x;
            float v1 = fmaxf(b0.y, 0.f) + s0.y;
            float v2 = fmaxf(b1.x, 0.f) + s1.x;
            float v3 = fmaxf(b1.y, 0.f) + s1.y;
            mx[ci] = fmaxf(fmaxf(v0, v1), fmaxf(v2, v3));
        }
#pragma unroll
        for (int off = 8; off >= 1; off >>= 1) {
#pragma unroll
            for (int i = 0; i < 8; ++i)
                mx[i] = fmaxf(mx[i], __shfl_xor_sync(0xffffffffu, mx[i], off));
        }
        if (tk == 0) {
#pragma unroll
            for (int ci = 0; ci < 8; ++ci)
                sF[miA * 64 + cb + ci] = mx[ci];
        }
        __syncthreads();

        // ---- Phase F: out[o][m] (12 warps: one (mi,o) each) ----
        if (w < 12) {
            const float* pxn = pre_xyz + n_ * 3 * M_;
            int m = m0 + fo_mi;
            float p = wo0 * sF[fo_mi * 64 + lane] + wo1 * sF[fo_mi * 64 + 32 + lane];
#pragma unroll
            for (int off = 16; off >= 1; off >>= 1)
                p += __shfl_xor_sync(0xffffffffu, p, off);
            if (lane == 0) {
                p += wx * pxn[m] + wy * pxn[M_ + m] + wz * pxn[2 * M_ + m];
                out[n_ * 3 * M_ + fo_o * M_ + m] = p;
            }
        }
    }
}

// ---------------- launcher ----------------
extern "C" void kernel_launch(void* const* d_in, const int* in_sizes, int n_in,
                              void* d_out, int out_size)
{
    const float* query     = (const float*)d_in[0];
    const float* scene_rgb = (const float*)d_in[1];
    const float* scene_xyz = (const float*)d_in[2];
    const float* pre_xyz   = (const float*)d_in[3];
    const float* mask      = (const float*)d_in[4];
    const float* W0        = (const float*)d_in[5];
    const float* g0        = (const float*)d_in[6];
    const float* b0        = (const float*)d_in[7];
    const float* m0        = (const float*)d_in[8];
    const float* v0        = (const float*)d_in[9];
    const float* W1a       = (const float*)d_in[10];
    const float* g1a       = (const float*)d_in[11];
    const float* b1a       = (const float*)d_in[12];
    const float* m1a       = (const float*)d_in[13];
    const float* v1a       = (const float*)d_in[14];
    const float* W1b       = (const float*)d_in[15];
    const float* g1b       = (const float*)d_in[16];
    const float* b1b       = (const float*)d_in[17];
    const float* m1b       = (const float*)d_in[18];
    const float* v1b       = (const float*)d_in[19];
    const float* Wskip     = (const float*)d_in[20];
    const float* Wout      = (const float*)d_in[21];
    float* out = (float*)d_out;

    prep_weights<<<1, 256>>>(W1a, W1b, Wskip,
                             g0, b0, m0, v0,
                             g1a, b1a, m1a, v1a,
                             g1b, b1b, m1b, v1b);
    prep_nk<<<(N_ * C_ * K_) / 256, 256>>>(scene_rgb, scene_xyz, mask,
                                           W0, W1a, Wskip);
    prep_B0t<<<N_ * 150, 128>>>(query, W0);

    cudaFuncSetAttribute(fused_main, cudaFuncAttributeMaxDynamicSharedMemorySize,
                         SMEM_FLOATS * 4);
    fused_main<<<1200, 512, SMEM_FLOATS * 4>>>(pre_xyz, Wout, out);
}

// round 9
// speedup vs baseline: 1.3192x; 1.3192x over previous
#include <cuda_runtime.h>
#include <cstdint>

// Problem constants
#define N_ 2
#define C_ 64
#define M_ 4800
#define K_ 64
#define EPS_ 1e-5f

// ---------------- device scratch (no allocation allowed) ----------------
__device__ __align__(16) float g_B0t[N_ * M_ * C_];  // s0[c]*(W0q@query), [n][m][c]
__device__ __align__(16) float g_A0p[N_ * C_ * K_];  // s0*(W0s@scene)+t0  [n][j][k]
__device__ __align__(16) float g_Ts [N_ * C_ * K_];  // Wskip_xyz @ sx     [n][c][k]
__device__ __align__(16) float g_T1a[N_ * C_ * K_];  // s1a*(W1a_xyz@sx)+t1a [n][c][k]
// tf32 weight bit-patterns (row-major)
__device__ __align__(16) unsigned g_W1u[128 * 64];   // [Wskip ; s1a*W1a]
__device__ __align__(16) unsigned g_W2u[64 * 64];    // s1b*W1b
__device__ float g_t1b[C_];
__device__ float g_s0[C_], g_t0[C_], g_s1a[C_], g_t1a[C_];

// ---------------- helpers ----------------
__device__ __forceinline__ unsigned f2tf(float x) {
    unsigned u;
    asm("cvt.rna.tf32.f32 %0, %1;" : "=r"(u) : "f"(x));
    return u;
}

__device__ __forceinline__ void mma_tf32(float d[4], const unsigned a[4],
                                         unsigned b0, unsigned b1) {
    asm volatile(
        "mma.sync.aligned.m16n8k8.row.col.f32.tf32.tf32.f32 "
        "{%0,%1,%2,%3}, {%4,%5,%6,%7}, {%8,%9}, {%0,%1,%2,%3};"
        : "+f"(d[0]), "+f"(d[1]), "+f"(d[2]), "+f"(d[3])
        : "r"(a[0]), "r"(a[1]), "r"(a[2]), "r"(a[3]), "r"(b0), "r"(b1));
}

// ---------------- prep 1: BN folds + tf32 weights ----------------
__global__ void prep_weights(
    const float* __restrict__ W1a, const float* __restrict__ W1b,
    const float* __restrict__ Wskip,
    const float* __restrict__ g0, const float* __restrict__ b0,
    const float* __restrict__ m0, const float* __restrict__ v0,
    const float* __restrict__ g1a, const float* __restrict__ b1a,
    const float* __restrict__ m1a, const float* __restrict__ v1a,
    const float* __restrict__ g1b, const float* __restrict__ b1b,
    const float* __restrict__ m1b, const float* __restrict__ v1b)
{
    __shared__ float s1a_s[C_], s1b_s[C_];
    int t = threadIdx.x;
    if (t < C_) {
        float s = g0[t] * rsqrtf(v0[t] + EPS_);
        g_s0[t] = s; g_t0[t] = b0[t] - m0[t] * s;
        float sa = g1a[t] * rsqrtf(v1a[t] + EPS_);
        s1a_s[t] = sa; g_s1a[t] = sa; g_t1a[t] = b1a[t] - m1a[t] * sa;
        float sb = g1b[t] * rsqrtf(v1b[t] + EPS_);
        s1b_s[t] = sb;
        g_t1b[t] = b1b[t] - m1b[t] * sb;
    }
    __syncthreads();
    for (int i = t; i < 128 * 64; i += blockDim.x) {
        int r = i >> 6, j = i & 63;
        float v1 = (r < 64) ? Wskip[r * 67 + j]
                            : s1a_s[r - 64] * W1a[(r - 64) * 67 + j];
        g_W1u[i] = f2tf(v1);
        if (r < 64)
            g_W2u[i] = f2tf(s1b_s[r] * W1b[r * 64 + j]);
    }
}

// ---------------- prep 2: per-(n,k) tensors (A0', Ts, T1a') ----------------
__global__ void prep_nk(
    const float* __restrict__ scene_rgb,   // (N,C,1,K)
    const float* __restrict__ scene_xyz,   // (N,3,1,K)
    const float* __restrict__ mask,        // (N,1,1,K)
    const float* __restrict__ W0,          // (C,2C)
    const float* __restrict__ W1a,         // (C,C+3)
    const float* __restrict__ Wskip)       // (C,C+3)
{
    int gid = blockIdx.x * blockDim.x + threadIdx.x;   // 0 .. N*C*K-1 = 8191
    int n = gid >> 12;
    int r = gid & 4095;
    int c = r >> 6;
    int k = r & 63;
    const float* sc = scene_rgb + n * C_ * K_;
    float acc = 0.f;
#pragma unroll 8
    for (int j = 0; j < C_; ++j)
        acc = fmaf(W0[c * 2 * C_ + j], sc[j * K_ + k], acc);
    g_A0p[gid] = g_s0[c] * acc + g_t0[c];

    float mk = mask[n * K_ + k];
    float x0 = scene_xyz[n * 3 * K_ + 0 * K_ + k] * mk;
    float x1 = scene_xyz[n * 3 * K_ + 1 * K_ + k] * mk;
    float x2 = scene_xyz[n * 3 * K_ + 2 * K_ + k] * mk;
    g_Ts[gid]  = Wskip[c * 67 + 64] * x0 + Wskip[c * 67 + 65] * x1 +
                 Wskip[c * 67 + 66] * x2;
    g_T1a[gid] = g_s1a[c] * (W1a[c * 67 + 64] * x0 + W1a[c * 67 + 65] * x1 +
                             W1a[c * 67 + 66] * x2) + g_t1a[c];
}

// ---------------- prep 3: B0t[n][m][c] (transposed, smem-tiled) ----------------
__global__ void __launch_bounds__(128) prep_B0t(
    const float* __restrict__ query,   // (N,C,M,1)
    const float* __restrict__ W0)      // (C,2C)
{
    __shared__ float sq[64 * 32];
    __shared__ float sw[64 * 64];
    const int tid = threadIdx.x;
    const int bid = blockIdx.x;
    const int n = bid / 150;
    const int m0 = (bid % 150) * 32;

    for (int i = tid; i < 4096; i += 128) {
        int c = i >> 6, j = i & 63;
        sw[j * 64 + c] = W0[c * 2 * C_ + C_ + j];
    }
    const float* qn = query + n * C_ * M_;
    for (int i = tid; i < 2048; i += 128) {
        int j = i >> 5, ml = i & 31;
        sq[i] = qn[j * M_ + m0 + ml];
    }
    __syncthreads();

    const int ml = tid & 31;
    const int cg = tid >> 5;
    float acc[16];
#pragma unroll
    for (int i = 0; i < 16; ++i) acc[i] = 0.f;
#pragma unroll 4
    for (int j = 0; j < 64; ++j) {
        float qv = sq[j * 32 + ml];
        const float4* wr = reinterpret_cast<const float4*>(sw + j * 64 + cg * 16);
        float4 w0 = wr[0], w1 = wr[1], w2 = wr[2], w3 = wr[3];
        float wv[16] = {w0.x, w0.y, w0.z, w0.w, w1.x, w1.y, w1.z, w1.w,
                        w2.x, w2.y, w2.z, w2.w, w3.x, w3.y, w3.z, w3.w};
#pragma unroll
        for (int ci = 0; ci < 16; ++ci)
            acc[ci] = fmaf(wv[ci], qv, acc[ci]);
    }
    float* outp = g_B0t + n * M_ * C_ + (m0 + ml) * C_ + cg * 16;
#pragma unroll
    for (int ci = 0; ci < 16; ++ci)
        outp[ci] = acc[ci] * g_s0[cg * 16 + ci];
}

// ---------------- fused main kernel (mma.sync tf32) ----------------
// 512 threads, CTA = one m-tile (Tm=2; n-cols = mi*64 + k, 128 total).
// H stored in smem as B-fragments: for j-block jb and in-block quad t,
// the pair (j = jb*8+t, j+4) is interleaved: uint index
// ((jb*4+t)*132 + n)*2 + s  -> each B-frag is one conflict-free LDS.64.
// GEMM1: [Wskip; s1a*W1a](128x64j) @ H -> skip rows & H1 rows.
// GEMM2: s1b*W1b(64x64c) @ H1.
// Weight A-fragments live in registers (loaded once per CTA).
// smem floats: sHs 8448 | sSkip 64*136=8704 | sPM 256 | sF 128  = 17536 f
#define SHS_F 0
#define SSK_F 8448
#define SPM_F 17152
#define SF_F  17408
#define SMEM_FLOATS 17536

extern "C" __global__ void __launch_bounds__(512) fused_main(
    const float* __restrict__ pre_xyz,   // (N,3,M)
    const float* __restrict__ Wout,      // (3,C+3)
    float* __restrict__ out)             // (N,3,M)
{
    extern __shared__ float smem[];
    unsigned* sHs  = reinterpret_cast<unsigned*>(smem + SHS_F);
    float*    sSkip = smem + SSK_F;
    float*    sPM   = smem + SPM_F;
    float*    sF    = smem + SF_F;

    const int tid  = threadIdx.x;
    const int lane = tid & 31;
    const int w    = tid >> 5;          // 0..15
    const int g    = lane >> 2;         // fragment group 0..7
    const int tq   = lane & 3;          // fragment quad-thread 0..3

    const int t   = blockIdx.x;         // 0..4799
    const int n_  = t / (M_ / 2);
    const int m0  = (t % (M_ / 2)) * 2;

    const float* A0n = g_A0p + n_ * 4096;
    const float* B0n = g_B0t + n_ * M_ * C_;
    const float* TsN = g_Ts  + n_ * 4096;
    const float* TaN = g_T1a + n_ * 4096;

    // ---- GEMM1 A-fragments (registers, once) ----
    const int rb = w >> 1;              // c'-row-block 0..7
    const int nh = w & 1;               // n-half
    unsigned wA1[8][4];
#pragma unroll
    for (int jb = 0; jb < 8; ++jb) {
        int base = (rb * 16 + g) * 64 + jb * 8 + tq;
        wA1[jb][0] = g_W1u[base];
        wA1[jb][1] = g_W1u[base + 8 * 64];
        wA1[jb][2] = g_W1u[base + 4];
        wA1[jb][3] = g_W1u[base + 8 * 64 + 4];
    }

    // ---- Phase A: build H (tf32) into B-frag layout ----
#pragma unroll
    for (int it = 0; it < 8; ++it) {
        int idx = tid + it * 512;       // 0..4095
        int n  = idx & 127;
        int q  = idx >> 7;              // 0..31
        int jb = q >> 2, tqq = q & 3;
        int j1 = jb * 8 + tqq, j2 = j1 + 4;
        int mi = n >> 6, k = n & 63;
        float b1 = B0n[(m0 + mi) * 64 + j1];
        float b2 = B0n[(m0 + mi) * 64 + j2];
        float h1 = fmaxf(A0n[j1 * 64 + k] + b1, 0.f);
        float h2 = fmaxf(A0n[j2 * 64 + k] + b2, 0.f);
        uint2 hv;
        hv.x = f2tf(h1);
        hv.y = f2tf(h2);
        *reinterpret_cast<uint2*>(sHs + (q * 132 + n) * 2) = hv;
    }
    __syncthreads();

    // ---- GEMM1 mma (results held in regs) ----
    float dall[32];
    {
        const uint2* hb = reinterpret_cast<const uint2*>(sHs);
#pragma unroll
        for (int nt = 0; nt < 8; ++nt) {
            int n = nh * 64 + nt * 8;
            float d[4] = {0.f, 0.f, 0.f, 0.f};
#pragma unroll
            for (int jb = 0; jb < 8; ++jb) {
                uint2 bv = hb[(jb * 4 + tq) * 132 + n + g];
                mma_tf32(d, wA1[jb], bv.x, bv.y);
            }
            dall[nt * 4 + 0] = d[0];
            dall[nt * 4 + 1] = d[1];
            dall[nt * 4 + 2] = d[2];
            dall[nt * 4 + 3] = d[3];
        }
    }
    __syncthreads();   // all B-frag reads of sHs complete

    // ---- Writeback: skip rows -> sSkip, fcn1a rows -> H1 (tf32) -> sHs ----
    if (rb < 4) {
        const int c = rb * 16 + g;
#pragma unroll
        for (int nt = 0; nt < 8; ++nt) {
            int ccol = nh * 64 + nt * 8 + 2 * tq;
            int k = ccol & 63;
            float2 t0v = *reinterpret_cast<const float2*>(TsN + c * 64 + k);
            float2 t8v = *reinterpret_cast<const float2*>(TsN + (c + 8) * 64 + k);
            *reinterpret_cast<float2*>(sSkip + c * 136 + ccol) =
                make_float2(dall[nt * 4 + 0] + t0v.x, dall[nt * 4 + 1] + t0v.y);
            *reinterpret_cast<float2*>(sSkip + (c + 8) * 136 + ccol) =
                make_float2(dall[nt * 4 + 2] + t8v.x, dall[nt * 4 + 3] + t8v.y);
        }
    } else {
        const int c  = (rb - 4) * 16 + g;
        const int c8 = c + 8;
        const int q0 = ((c  >> 3) << 2) + (c  & 3), s0 = (c  >> 2) & 1;
        const int q8 = ((c8 >> 3) << 2) + (c8 & 3), s8 = (c8 >> 2) & 1;
#pragma unroll
        for (int nt = 0; nt < 8; ++nt) {
            int ccol = nh * 64 + nt * 8 + 2 * tq;
            int k = ccol & 63;
            float2 a0v = *reinterpret_cast<const float2*>(TaN + c * 64 + k);
            float2 a8v = *reinterpret_cast<const float2*>(TaN + c8 * 64 + k);
            sHs[(q0 * 132 + ccol) * 2 + s0] =
                f2tf(fmaxf(dall[nt * 4 + 0] + a0v.x, 0.f));
            sHs[(q0 * 132 + ccol + 1) * 2 + s0] =
                f2tf(fmaxf(dall[nt * 4 + 1] + a0v.y, 0.f));
            sHs[(q8 * 132 + ccol) * 2 + s8] =
                f2tf(fmaxf(dall[nt * 4 + 2] + a8v.x, 0.f));
            sHs[(q8 * 132 + ccol + 1) * 2 + s8] =
                f2tf(fmaxf(dall[nt * 4 + 3] + a8v.y, 0.f));
        }
    }

    // ---- GEMM2 A-fragments + bias (after wA1 is dead) ----
    const int rb2 = w & 3;
    const int qtr = w >> 2;             // n-quarter 0..3 (mi = qtr>>1)
    unsigned wA2[8][4];
#pragma unroll
    for (int jb = 0; jb < 8; ++jb) {
        int base = (rb2 * 16 + g) * 64 + jb * 8 + tq;
        wA2[jb][0] = g_W2u[base];
        wA2[jb][1] = g_W2u[base + 8 * 64];
        wA2[jb][2] = g_W2u[base + 4];
        wA2[jb][3] = g_W2u[base + 8 * 64 + 4];
    }
    const float t1bg  = g_t1b[rb2 * 16 + g];
    const float t1bg8 = g_t1b[rb2 * 16 + g + 8];
    __syncthreads();   // H1 + sSkip complete

    // ---- GEMM2 + combine + k-max ----
    float mxg = -3.4e38f, mxg8 = -3.4e38f;
    {
        const uint2* hb = reinterpret_cast<const uint2*>(sHs);
        const int c = rb2 * 16 + g;
#pragma unroll
        for (int nt2 = 0; nt2 < 4; ++nt2) {
            int n = qtr * 32 + nt2 * 8;
            float d[4] = {t1bg, t1bg, t1bg8, t1bg8};
#pragma unroll
            for (int jb = 0; jb < 8; ++jb) {
                uint2 bv = hb[(jb * 4 + tq) * 132 + n + g];
                mma_tf32(d, wA2[jb], bv.x, bv.y);
            }
            int ccol = n + 2 * tq;
            float2 sk0 = *reinterpret_cast<const float2*>(sSkip + c * 136 + ccol);
            float2 sk8 = *reinterpret_cast<const float2*>(sSkip + (c + 8) * 136 + ccol);
            float v0 = fmaxf(d[0], 0.f) + sk0.x;
            float v1 = fmaxf(d[1], 0.f) + sk0.y;
            float v2 = fmaxf(d[2], 0.f) + sk8.x;
            float v3 = fmaxf(d[3], 0.f) + sk8.y;
            mxg  = fmaxf(mxg,  fmaxf(v0, v1));
            mxg8 = fmaxf(mxg8, fmaxf(v2, v3));
        }
    }
    mxg  = fmaxf(mxg,  __shfl_xor_sync(0xffffffffu, mxg, 1));
    mxg  = fmaxf(mxg,  __shfl_xor_sync(0xffffffffu, mxg, 2));
    mxg8 = fmaxf(mxg8, __shfl_xor_sync(0xffffffffu, mxg8, 1));
    mxg8 = fmaxf(mxg8, __shfl_xor_sync(0xffffffffu, mxg8, 2));
    if (tq == 0) {
        sPM[(rb2 * 16 + g) * 4 + qtr]     = mxg;
        sPM[(rb2 * 16 + g + 8) * 4 + qtr] = mxg8;
    }
    __syncthreads();

    // ---- finalize max per (c, mi) ----
    if (tid < 128) {
        int c = tid & 63, mi = tid >> 6;
        sF[mi * 64 + c] = fmaxf(sPM[c * 4 + 2 * mi], sPM[c * 4 + 2 * mi + 1]);
    }
    __syncthreads();

    // ---- output: out[n][o][m] = Wout[o,:64]@sF + Wout[o,64:67]@pre_xyz ----
    if (w < 6) {
        const int fo_mi = w / 3, fo_o = w - fo_mi * 3;
        const float* pxn = pre_xyz + n_ * 3 * M_;
        int m = m0 + fo_mi;
        float p = Wout[fo_o * 67 + lane] * sF[fo_mi * 64 + lane] +
                  Wout[fo_o * 67 + 32 + lane] * sF[fo_mi * 64 + 32 + lane];
#pragma unroll
        for (int off = 16; off >= 1; off >>= 1)
            p += __shfl_xor_sync(0xffffffffu, p, off);
        if (lane == 0) {
            p += Wout[fo_o * 67 + 64] * pxn[m] +
                 Wout[fo_o * 67 + 65] * pxn[M_ + m] +
                 Wout[fo_o * 67 + 66] * pxn[2 * M_ + m];
            out[n_ * 3 * M_ + fo_o * M_ + m] = p;
        }
    }
}

// ---------------- launcher ----------------
extern "C" void kernel_launch(void* const* d_in, const int* in_sizes, int n_in,
                              void* d_out, int out_size)
{
    const float* query     = (const float*)d_in[0];
    const float* scene_rgb = (const float*)d_in[1];
    const float* scene_xyz = (const float*)d_in[2];
    const float* pre_xyz   = (const float*)d_in[3];
    const float* mask      = (const float*)d_in[4];
    const float* W0        = (const float*)d_in[5];
    const float* g0        = (const float*)d_in[6];
    const float* b0        = (const float*)d_in[7];
    const float* m0        = (const float*)d_in[8];
    const float* v0        = (const float*)d_in[9];
    const float* W1a       = (const float*)d_in[10];
    const float* g1a       = (const float*)d_in[11];
    const float* b1a       = (const float*)d_in[12];
    const float* m1a       = (const float*)d_in[13];
    const float* v1a       = (const float*)d_in[14];
    const float* W1b       = (const float*)d_in[15];
    const float* g1b       = (const float*)d_in[16];
    const float* b1b       = (const float*)d_in[17];
    const float* m1b       = (const float*)d_in[18];
    const float* v1b       = (const float*)d_in[19];
    const float* Wskip     = (const float*)d_in[20];
    const float* Wout      = (const float*)d_in[21];
    float* out = (float*)d_out;

    prep_weights<<<1, 256>>>(W1a, W1b, Wskip,
                             g0, b0, m0, v0,
                             g1a, b1a, m1a, v1a,
                             g1b, b1b, m1b, v1b);
    prep_nk<<<(N_ * C_ * K_) / 256, 256>>>(scene_rgb, scene_xyz, mask,
                                           W0, W1a, Wskip);
    prep_B0t<<<N_ * 150, 128>>>(query, W0);

    cudaFuncSetAttribute(fused_main, cudaFuncAttributeMaxDynamicSharedMemorySize,
                         SMEM_FLOATS * 4);
    fused_main<<<N_ * (M_ / 2), 512, SMEM_FLOATS * 4>>>(pre_xyz, Wout, out);
}

// round 10
// speedup vs baseline: 1.4485x; 1.0980x over previous
#include <cuda_runtime.h>
#include <cstdint>

// Problem constants
#define N_ 2
#define C_ 64
#define M_ 4800
#define K_ 64
#define EPS_ 1e-5f

// ---------------- device scratch (no allocation allowed) ----------------
__device__ __align__(16) float g_B0t[N_ * M_ * C_];  // s0[c]*(W0q@query), [n][m][c]
__device__ __align__(16) float g_A0p[N_ * C_ * K_];  // s0*(W0s@scene)+t0  [n][j][k]
__device__ __align__(16) float g_Ts [N_ * C_ * K_];  // Wskip_xyz @ sx     [n][c][k]
__device__ __align__(16) float g_T1a[N_ * C_ * K_];  // s1a*(W1a_xyz@sx)+t1a [n][c][k]
// tf32 weight bit-patterns (row-major)
__device__ __align__(16) unsigned g_W1u[128 * 64];   // [Wskip ; s1a*W1a]
__device__ __align__(16) unsigned g_W2u[64 * 64];    // s1b*W1b
__device__ float g_t1b[C_];
__device__ float g_s0[C_], g_t0[C_], g_s1a[C_], g_t1a[C_];

// ---------------- helpers ----------------
__device__ __forceinline__ unsigned f2tf(float x) {
    unsigned u;
    asm("cvt.rna.tf32.f32 %0, %1;" : "=r"(u) : "f"(x));
    return u;
}

__device__ __forceinline__ void mma_tf32(float d[4], const unsigned a[4],
                                         unsigned b0, unsigned b1) {
    asm volatile(
        "mma.sync.aligned.m16n8k8.row.col.f32.tf32.tf32.f32 "
        "{%0,%1,%2,%3}, {%4,%5,%6,%7}, {%8,%9}, {%0,%1,%2,%3};"
        : "+f"(d[0]), "+f"(d[1]), "+f"(d[2]), "+f"(d[3])
        : "r"(a[0]), "r"(a[1]), "r"(a[2]), "r"(a[3]), "r"(b0), "r"(b1));
}

// ---------------- prep 1: BN folds + tf32 weights ----------------
__global__ void prep_weights(
    const float* __restrict__ W1a, const float* __restrict__ W1b,
    const float* __restrict__ Wskip,
    const float* __restrict__ g0, const float* __restrict__ b0,
    const float* __restrict__ m0, const float* __restrict__ v0,
    const float* __restrict__ g1a, const float* __restrict__ b1a,
    const float* __restrict__ m1a, const float* __restrict__ v1a,
    const float* __restrict__ g1b, const float* __restrict__ b1b,
    const float* __restrict__ m1b, const float* __restrict__ v1b)
{
    __shared__ float s1a_s[C_], s1b_s[C_];
    int t = threadIdx.x;
    if (t < C_) {
        float s = g0[t] * rsqrtf(v0[t] + EPS_);
        g_s0[t] = s; g_t0[t] = b0[t] - m0[t] * s;
        float sa = g1a[t] * rsqrtf(v1a[t] + EPS_);
        s1a_s[t] = sa; g_s1a[t] = sa; g_t1a[t] = b1a[t] - m1a[t] * sa;
        float sb = g1b[t] * rsqrtf(v1b[t] + EPS_);
        s1b_s[t] = sb;
        g_t1b[t] = b1b[t] - m1b[t] * sb;
    }
    __syncthreads();
    for (int i = t; i < 128 * 64; i += blockDim.x) {
        int r = i >> 6, j = i & 63;
        float v1 = (r < 64) ? Wskip[r * 67 + j]
                            : s1a_s[r - 64] * W1a[(r - 64) * 67 + j];
        g_W1u[i] = f2tf(v1);
        if (r < 64)
            g_W2u[i] = f2tf(s1b_s[r] * W1b[r * 64 + j]);
    }
}

// ---------------- prep 2: per-(n,k) tensors (A0', Ts, T1a') ----------------
__global__ void prep_nk(
    const float* __restrict__ scene_rgb,   // (N,C,1,K)
    const float* __restrict__ scene_xyz,   // (N,3,1,K)
    const float* __restrict__ mask,        // (N,1,1,K)
    const float* __restrict__ W0,          // (C,2C)
    const float* __restrict__ W1a,         // (C,C+3)
    const float* __restrict__ Wskip)       // (C,C+3)
{
    int gid = blockIdx.x * blockDim.x + threadIdx.x;   // 0 .. N*C*K-1 = 8191
    int n = gid >> 12;
    int r = gid & 4095;
    int c = r >> 6;
    int k = r & 63;
    const float* sc = scene_rgb + n * C_ * K_;
    float acc = 0.f;
#pragma unroll 8
    for (int j = 0; j < C_; ++j)
        acc = fmaf(W0[c * 2 * C_ + j], sc[j * K_ + k], acc);
    g_A0p[gid] = g_s0[c] * acc + g_t0[c];

    float mk = mask[n * K_ + k];
    float x0 = scene_xyz[n * 3 * K_ + 0 * K_ + k] * mk;
    float x1 = scene_xyz[n * 3 * K_ + 1 * K_ + k] * mk;
    float x2 = scene_xyz[n * 3 * K_ + 2 * K_ + k] * mk;
    g_Ts[gid]  = Wskip[c * 67 + 64] * x0 + Wskip[c * 67 + 65] * x1 +
                 Wskip[c * 67 + 66] * x2;
    g_T1a[gid] = g_s1a[c] * (W1a[c * 67 + 64] * x0 + W1a[c * 67 + 65] * x1 +
                             W1a[c * 67 + 66] * x2) + g_t1a[c];
}

// ---------------- prep 3: B0t[n][m][c] (transposed, smem-tiled) ----------------
__global__ void __launch_bounds__(128) prep_B0t(
    const float* __restrict__ query,   // (N,C,M,1)
    const float* __restrict__ W0)      // (C,2C)
{
    __shared__ float sq[64 * 32];
    __shared__ float sw[64 * 64];
    const int tid = threadIdx.x;
    const int bid = blockIdx.x;
    const int n = bid / 150;
    const int m0 = (bid % 150) * 32;

    for (int i = tid; i < 4096; i += 128) {
        int c = i >> 6, j = i & 63;
        sw[j * 64 + c] = W0[c * 2 * C_ + C_ + j];
    }
    const float* qn = query + n * C_ * M_;
    for (int i = tid; i < 2048; i += 128) {
        int j = i >> 5, ml = i & 31;
        sq[i] = qn[j * M_ + m0 + ml];
    }
    __syncthreads();

    const int ml = tid & 31;
    const int cg = tid >> 5;
    float acc[16];
#pragma unroll
    for (int i = 0; i < 16; ++i) acc[i] = 0.f;
#pragma unroll 4
    for (int j = 0; j < 64; ++j) {
        float qv = sq[j * 32 + ml];
        const float4* wr = reinterpret_cast<const float4*>(sw + j * 64 + cg * 16);
        float4 w0 = wr[0], w1 = wr[1], w2 = wr[2], w3 = wr[3];
        float wv[16] = {w0.x, w0.y, w0.z, w0.w, w1.x, w1.y, w1.z, w1.w,
                        w2.x, w2.y, w2.z, w2.w, w3.x, w3.y, w3.z, w3.w};
#pragma unroll
        for (int ci = 0; ci < 16; ++ci)
            acc[ci] = fmaf(wv[ci], qv, acc[ci]);
    }
    float* outp = g_B0t + n * M_ * C_ + (m0 + ml) * C_ + cg * 16;
#pragma unroll
    for (int ci = 0; ci < 16; ++ci)
        outp[ci] = acc[ci] * g_s0[cg * 16 + ci];
}

// ---------------- fused main kernel (mma.sync tf32, 2 CTAs/SM) ----------------
// 512 threads, CTA = one m-tile (Tm=2; n-cols = mi*64 + k, 128 total).
// H (and H1) stored as B-fragments: for j-block jb and in-block quad t,
// the pair (j = jb*8+t, j+4) interleaved at uint index ((jb*4+t)*132+n)*2+s.
// GEMM1: [Wskip; s1a*W1a](128x64j) @ H. Each nt-chain's d[4] is written back
// IMMEDIATELY (skip->sSkip(+Ts), fcn1a->relu(+T1a)->tf32->sHs2) -- no
// registers held across barriers -> 2 CTAs/SM for phase overlap.
// GEMM2: s1b*W1b(64x64c) @ H1 (from sHs2) + t1b, relu, +skip, k-max.
// smem floats: sHs 8448 | sHs2 8448 | sSkip 8704 | sPM 256 | sF 128
#define SHS_F  0
#define SHS2_F 8448
#define SSK_F  16896
#define SPM_F  25600
#define SF_F   25856
#define SMEM_FLOATS 25984

extern "C" __global__ void __launch_bounds__(512, 2) fused_main(
    const float* __restrict__ pre_xyz,   // (N,3,M)
    const float* __restrict__ Wout,      // (3,C+3)
    float* __restrict__ out)             // (N,3,M)
{
    extern __shared__ float smem[];
    unsigned* sHs   = reinterpret_cast<unsigned*>(smem + SHS_F);
    unsigned* sHs2  = reinterpret_cast<unsigned*>(smem + SHS2_F);
    float*    sSkip = smem + SSK_F;
    float*    sPM   = smem + SPM_F;
    float*    sF    = smem + SF_F;

    const int tid  = threadIdx.x;
    const int lane = tid & 31;
    const int w    = tid >> 5;          // 0..15
    const int g    = lane >> 2;         // fragment group 0..7
    const int tq   = lane & 3;          // fragment quad-thread 0..3

    const int t   = blockIdx.x;         // 0..4799
    const int n_  = t / (M_ / 2);
    const int m0  = (t % (M_ / 2)) * 2;

    const float* A0n = g_A0p + n_ * 4096;
    const float* B0n = g_B0t + n_ * M_ * C_;
    const float* TsN = g_Ts  + n_ * 4096;
    const float* TaN = g_T1a + n_ * 4096;

    // ---- GEMM1 A-fragments (registers, once) ----
    const int rb = w >> 1;              // row-block 0..7 (0-3 skip, 4-7 fcn1a)
    const int nh = w & 1;               // n-half
    unsigned wA1[8][4];
#pragma unroll
    for (int jb = 0; jb < 8; ++jb) {
        int base = (rb * 16 + g) * 64 + jb * 8 + tq;
        wA1[jb][0] = g_W1u[base];
        wA1[jb][1] = g_W1u[base + 8 * 64];
        wA1[jb][2] = g_W1u[base + 4];
        wA1[jb][3] = g_W1u[base + 8 * 64 + 4];
    }

    // ---- Phase A: build H (tf32) into B-frag layout ----
#pragma unroll
    for (int it = 0; it < 8; ++it) {
        int idx = tid + it * 512;       // 0..4095
        int n  = idx & 127;
        int q  = idx >> 7;              // 0..31
        int jb = q >> 2, tqq = q & 3;
        int j1 = jb * 8 + tqq, j2 = j1 + 4;
        int mi = n >> 6, k = n & 63;
        float b1 = B0n[(m0 + mi) * 64 + j1];
        float b2 = B0n[(m0 + mi) * 64 + j2];
        float h1 = fmaxf(A0n[j1 * 64 + k] + b1, 0.f);
        float h2 = fmaxf(A0n[j2 * 64 + k] + b2, 0.f);
        uint2 hv;
        hv.x = f2tf(h1);
        hv.y = f2tf(h2);
        *reinterpret_cast<uint2*>(sHs + (q * 132 + n) * 2) = hv;
    }
    __syncthreads();

    // ---- GEMM1 mma with immediate per-nt writeback ----
    {
        const uint2* hb = reinterpret_cast<const uint2*>(sHs);
        if (rb < 4) {
            // skip rows: c = rb*16+g (+8)
            const int c = rb * 16 + g;
#pragma unroll
            for (int nt = 0; nt < 8; ++nt) {
                int n = nh * 64 + nt * 8;
                float d[4] = {0.f, 0.f, 0.f, 0.f};
#pragma unroll
                for (int jb = 0; jb < 8; ++jb) {
                    uint2 bv = hb[(jb * 4 + tq) * 132 + n + g];
                    mma_tf32(d, wA1[jb], bv.x, bv.y);
                }
                int ccol = n + 2 * tq;
                int k = ccol & 63;
                float2 t0v = *reinterpret_cast<const float2*>(TsN + c * 64 + k);
                float2 t8v = *reinterpret_cast<const float2*>(TsN + (c + 8) * 64 + k);
                *reinterpret_cast<float2*>(sSkip + c * 136 + ccol) =
                    make_float2(d[0] + t0v.x, d[1] + t0v.y);
                *reinterpret_cast<float2*>(sSkip + (c + 8) * 136 + ccol) =
                    make_float2(d[2] + t8v.x, d[3] + t8v.y);
            }
        } else {
            // fcn1a rows: H1 = relu(v + T1a) -> tf32 -> sHs2 (B-frag layout)
            const int c  = (rb - 4) * 16 + g;
            const int c8 = c + 8;
            const int q0 = ((c  >> 3) << 2) + (c  & 3), s0 = (c  >> 2) & 1;
            const int q8 = ((c8 >> 3) << 2) + (c8 & 3), s8 = (c8 >> 2) & 1;
#pragma unroll
            for (int nt = 0; nt < 8; ++nt) {
                int n = nh * 64 + nt * 8;
                float d[4] = {0.f, 0.f, 0.f, 0.f};
#pragma unroll
                for (int jb = 0; jb < 8; ++jb) {
                    uint2 bv = hb[(jb * 4 + tq) * 132 + n + g];
                    mma_tf32(d, wA1[jb], bv.x, bv.y);
                }
                int ccol = n + 2 * tq;
                int k = ccol & 63;
                float2 a0v = *reinterpret_cast<const float2*>(TaN + c * 64 + k);
                float2 a8v = *reinterpret_cast<const float2*>(TaN + c8 * 64 + k);
                sHs2[(q0 * 132 + ccol) * 2 + s0] =
                    f2tf(fmaxf(d[0] + a0v.x, 0.f));
                sHs2[(q0 * 132 + ccol + 1) * 2 + s0] =
                    f2tf(fmaxf(d[1] + a0v.y, 0.f));
                sHs2[(q8 * 132 + ccol) * 2 + s8] =
                    f2tf(fmaxf(d[2] + a8v.x, 0.f));
                sHs2[(q8 * 132 + ccol + 1) * 2 + s8] =
                    f2tf(fmaxf(d[3] + a8v.y, 0.f));
            }
        }
    }

    // ---- GEMM2 A-fragments + bias (wA1 dead) ----
    const int rb2 = w & 3;
    const int qtr = w >> 2;             // n-quarter 0..3 (mi = qtr>>1)
    unsigned wA2[8][4];
#pragma unroll
    for (int jb = 0; jb < 8; ++jb) {
        int base = (rb2 * 16 + g) * 64 + jb * 8 + tq;
        wA2[jb][0] = g_W2u[base];
        wA2[jb][1] = g_W2u[base + 8 * 64];
        wA2[jb][2] = g_W2u[base + 4];
        wA2[jb][3] = g_W2u[base + 8 * 64 + 4];
    }
    const float t1bg  = g_t1b[rb2 * 16 + g];
    const float t1bg8 = g_t1b[rb2 * 16 + g + 8];
    __syncthreads();   // H1 + sSkip complete

    // ---- GEMM2 + combine + k-max ----
    float mxg = -3.4e38f, mxg8 = -3.4e38f;
    {
        const uint2* hb2 = reinterpret_cast<const uint2*>(sHs2);
        const int c = rb2 * 16 + g;
#pragma unroll
        for (int nt2 = 0; nt2 < 4; ++nt2) {
            int n = qtr * 32 + nt2 * 8;
            float d[4] = {t1bg, t1bg, t1bg8, t1bg8};
#pragma unroll
            for (int jb = 0; jb < 8; ++jb) {
                uint2 bv = hb2[(jb * 4 + tq) * 132 + n + g];
                mma_tf32(d, wA2[jb], bv.x, bv.y);
            }
            int ccol = n + 2 * tq;
            float2 sk0 = *reinterpret_cast<const float2*>(sSkip + c * 136 + ccol);
            float2 sk8 = *reinterpret_cast<const float2*>(sSkip + (c + 8) * 136 + ccol);
            float v0 = fmaxf(d[0], 0.f) + sk0.x;
            float v1 = fmaxf(d[1], 0.f) + sk0.y;
            float v2 = fmaxf(d[2], 0.f) + sk8.x;
            float v3 = fmaxf(d[3], 0.f) + sk8.y;
            mxg  = fmaxf(mxg,  fmaxf(v0, v1));
            mxg8 = fmaxf(mxg8, fmaxf(v2, v3));
        }
    }
    mxg  = fmaxf(mxg,  __shfl_xor_sync(0xffffffffu, mxg, 1));
    mxg  = fmaxf(mxg,  __shfl_xor_sync(0xffffffffu, mxg, 2));
    mxg8 = fmaxf(mxg8, __shfl_xor_sync(0xffffffffu, mxg8, 1));
    mxg8 = fmaxf(mxg8, __shfl_xor_sync(0xffffffffu, mxg8, 2));
    if (tq == 0) {
        sPM[(rb2 * 16 + g) * 4 + qtr]     = mxg;
        sPM[(rb2 * 16 + g + 8) * 4 + qtr] = mxg8;
    }
    __syncthreads();

    // ---- finalize max per (c, mi) ----
    if (tid < 128) {
        int c = tid & 63, mi = tid >> 6;
        sF[mi * 64 + c] = fmaxf(sPM[c * 4 + 2 * mi], sPM[c * 4 + 2 * mi + 1]);
    }
    __syncthreads();

    // ---- output: out[n][o][m] = Wout[o,:64]@sF + Wout[o,64:67]@pre_xyz ----
    if (w < 6) {
        const int fo_mi = w / 3, fo_o = w - fo_mi * 3;
        const float* pxn = pre_xyz + n_ * 3 * M_;
        int m = m0 + fo_mi;
        float p = Wout[fo_o * 67 + lane] * sF[fo_mi * 64 + lane] +
                  Wout[fo_o * 67 + 32 + lane] * sF[fo_mi * 64 + 32 + lane];
#pragma unroll
        for (int off = 16; off >= 1; off >>= 1)
            p += __shfl_xor_sync(0xffffffffu, p, off);
        if (lane == 0) {
            p += Wout[fo_o * 67 + 64] * pxn[m] +
                 Wout[fo_o * 67 + 65] * pxn[M_ + m] +
                 Wout[fo_o * 67 + 66] * pxn[2 * M_ + m];
            out[n_ * 3 * M_ + fo_o * M_ + m] = p;
        }
    }
}

// ---------------- launcher ----------------
extern "C" void kernel_launch(void* const* d_in, const int* in_sizes, int n_in,
                              void* d_out, int out_size)
{
    const float* query     = (const float*)d_in[0];
    const float* scene_rgb = (const float*)d_in[1];
    const float* scene_xyz = (const float*)d_in[2];
    const float* pre_xyz   = (const float*)d_in[3];
    const float* mask      = (const float*)d_in[4];
    const float* W0        = (const float*)d_in[5];
    const float* g0        = (const float*)d_in[6];
    const float* b0        = (const float*)d_in[7];
    const float* m0        = (const float*)d_in[8];
    const float* v0        = (const float*)d_in[9];
    const float* W1a       = (const float*)d_in[10];
    const float* g1a       = (const float*)d_in[11];
    const float* b1a       = (const float*)d_in[12];
    const float* m1a       = (const float*)d_in[13];
    const float* v1a       = (const float*)d_in[14];
    const float* W1b       = (const float*)d_in[15];
    const float* g1b       = (const float*)d_in[16];
    const float* b1b       = (const float*)d_in[17];
    const float* m1b       = (const float*)d_in[18];
    const float* v1b       = (const float*)d_in[19];
    const float* Wskip     = (const float*)d_in[20];
    const float* Wout      = (const float*)d_in[21];
    float* out = (float*)d_out;

    prep_weights<<<1, 256>>>(W1a, W1b, Wskip,
                             g0, b0, m0, v0,
                             g1a, b1a, m1a, v1a,
                             g1b, b1b, m1b, v1b);
    prep_nk<<<(N_ * C_ * K_) / 256, 256>>>(scene_rgb, scene_xyz, mask,
                                           W0, W1a, Wskip);
    prep_B0t<<<N_ * 150, 128>>>(query, W0);

    cudaFuncSetAttribute(fused_main, cudaFuncAttributeMaxDynamicSharedMemorySize,
                         SMEM_FLOATS * 4);
    fused_main<<<N_ * (M_ / 2), 512, SMEM_FLOATS * 4>>>(pre_xyz, Wout, out);
}